// round 17
// baseline (speedup 1.0000x reference)
#include <cuda_runtime.h>
#include <cuda_bf16.h>
#include <math.h>
#include <stdint.h>

#define BATCH 8
#define DIMC  192
#define C3    576
#define NH    8
#define HD    24
#define IMH   128
#define IMW   128
#define HW    (IMH*IMW)
#define NSPLIT 32
#define KPA   384          // A row length: [hi 192 | lo 192]
#define NCHUNK 6           // k-chunks of 32

// ---------------- scratch (static __device__, zero-initialized) ----------------
static __device__ float g_qkv[BATCH * C3 * HW];                // 1x1 conv output (fp32)
static __device__ float g_dw [BATCH * C3 * HW];                // depthwise out (q,k fp32)
static __device__ float g_attn_part[NSPLIT * BATCH * NH * HD * HD];
static __device__ float g_np[NSPLIT * BATCH * NH * 2 * HD];
static __device__ float g_attn[BATCH * NH * HD * HD];
static __device__ __nv_bfloat16 g_w1[C3 * KPA];                // A gemm1 [576][hi|lo]
static __device__ __nv_bfloat16 g_m2[BATCH * DIMC * KPA];      // A gemm2 [192][hi|lo]
static __device__ __nv_bfloat16 g_xhi[BATCH * DIMC * HW];      // X hi plane [c][n]
static __device__ __nv_bfloat16 g_xlo[BATCH * DIMC * HW];      // X lo plane [c][n]
static __device__ __nv_bfloat16 g_vhi[BATCH * DIMC * HW];      // V hi plane [c][n]
static __device__ __nv_bfloat16 g_vlo[BATCH * DIMC * HW];      // V lo plane [c][n]

// ---------------- PTX helpers (sm_80-level only) ----------------
__device__ __forceinline__ uint32_t s2u(const void* p) {
    uint32_t a;
    asm("{ .reg .u64 t; cvta.to.shared.u64 t, %1; cvt.u32.u64 %0, t; }" : "=r"(a) : "l"(p));
    return a;
}
#define CP16(d, s) asm volatile("cp.async.cg.shared.global [%0], [%1], 16;" :: "r"(d), "l"(s))
#define CP_COMMIT() asm volatile("cp.async.commit_group;" ::: "memory")
#define LDSM4(r0, r1, r2, r3, a) \
    asm volatile("ldmatrix.sync.aligned.m8n8.x4.shared.b16 {%0,%1,%2,%3}, [%4];" \
                 : "=r"(r0), "=r"(r1), "=r"(r2), "=r"(r3) : "r"(a))
#define LDSM4T(r0, r1, r2, r3, a) \
    asm volatile("ldmatrix.sync.aligned.m8n8.x4.trans.shared.b16 {%0,%1,%2,%3}, [%4];" \
                 : "=r"(r0), "=r"(r1), "=r"(r2), "=r"(r3) : "r"(a))
#define MMA16816(d, a, b0, b1) \
    asm volatile("mma.sync.aligned.m16n8k16.row.col.f32.bf16.bf16.f32 " \
                 "{%0,%1,%2,%3}, {%4,%5,%6,%7}, {%8,%9}, {%0,%1,%2,%3};" \
                 : "+f"((d)[0]), "+f"((d)[1]), "+f"((d)[2]), "+f"((d)[3]) \
                 : "r"((a)[0]), "r"((a)[1]), "r"((a)[2]), "r"((a)[3]), \
                   "r"(b0), "r"(b1))

__device__ __forceinline__ uint32_t pkbf(float a, float b) {
    return ((uint32_t)__bfloat16_as_ushort(__float2bfloat16(b)) << 16) |
           (uint32_t)__bfloat16_as_ushort(__float2bfloat16(a));
}

// ===== merged GEMM, chunked split-bf16: per chunk {Ahi,Alo,Bhi,Blo}, 3 MMA passes =====
#define ASTR   80
#define BSTR   272
#define AOFF_LO (128 * ASTR)
#define BHOFF   (2 * 128 * ASTR)
#define BLOFF   (BHOFF + 32 * BSTR)
#define BUFSZ   (BLOFF + 32 * BSTR)
#define SMEM_G  (2 * BUFSZ)
__global__ __launch_bounds__(128, 2) void hmma_gemm(
    const __nv_bfloat16* __restrict__ A,
    const __nv_bfloat16* __restrict__ BHI, const __nv_bfloat16* __restrict__ BLO,
    float* __restrict__ C, int Mtot, long sA, long sBp, long sC)
{
    extern __shared__ __align__(16) char smdyn[];
    const uint32_t sb0 = s2u(smdyn);
    const int tid = threadIdx.x, lane = tid & 31, wid = tid >> 5;
    const int n0 = blockIdx.x << 7;
    const int m0 = blockIdx.y << 7;
    const bool full = (Mtot - m0) >= 128;
    const __nv_bfloat16* Ab  = A   + (long)blockIdx.z * sA;
    const __nv_bfloat16* Bhi = BHI + (long)blockIdx.z * sBp;
    const __nv_bfloat16* Blo = BLO + (long)blockIdx.z * sBp;
    float* Cb = C + (long)blockIdx.z * sC;

    const int a_r  = (lane & 7) + ((lane >> 3) & 1) * 8;
    const int a_ko = (lane >> 4) * 16;
    const int bt_k = (lane & 7) + (((lane >> 3) & 1) << 3);
    const int bt_n = (lane >> 4) * 16;
    const int wn = (wid & 1) << 6;

    auto loadB = [&](int j, uint32_t db) {
#pragma unroll
        for (int it = 0; it < 4; it++) {
            int row = (tid >> 4) + it * 8, seg = tid & 15;
            CP16(db + BHOFF + row * BSTR + seg * 16,
                 Bhi + (long)(j * 32 + row) * HW + n0 + seg * 8);
            CP16(db + BLOFF + row * BSTR + seg * 16,
                 Blo + (long)(j * 32 + row) * HW + n0 + seg * 8);
        }
    };

    if (full) {
        const int wm = (wid >> 1) << 6;
        float acc[4][8][4];
#pragma unroll
        for (int i = 0; i < 4; i++)
#pragma unroll
            for (int j = 0; j < 8; j++)
#pragma unroll
                for (int v = 0; v < 4; v++) acc[i][j][v] = 0.f;

        auto load_stage = [&](int j, uint32_t db) {
#pragma unroll
            for (int it = 0; it < 4; it++) {
                int row = (tid >> 2) + it * 32, seg = tid & 3;
                const __nv_bfloat16* arow = Ab + (long)(m0 + row) * KPA + j * 32 + seg * 8;
                CP16(db + row * ASTR + seg * 16, arow);
                CP16(db + AOFF_LO + row * ASTR + seg * 16, arow + 192);
            }
            loadB(j, db);
        };

        auto mma_pass = [&](uint32_t ab, uint32_t bb) {
#pragma unroll
            for (int ks = 0; ks < 2; ks++) {
                uint32_t ar[4][4], brT[4][4];
#pragma unroll
                for (int i = 0; i < 4; i++)
                    LDSM4(ar[i][0], ar[i][1], ar[i][2], ar[i][3],
                          ab + (wm + i * 16 + a_r) * ASTR + ks * 32 + a_ko);
#pragma unroll
                for (int j = 0; j < 4; j++)
                    LDSM4T(brT[j][0], brT[j][1], brT[j][2], brT[j][3],
                           bb + (ks * 16 + bt_k) * BSTR + wn * 2 + j * 32 + bt_n);
#pragma unroll
                for (int i = 0; i < 4; i++)
#pragma unroll
                    for (int jn = 0; jn < 8; jn++) {
                        int jj = jn >> 1, pr = jn & 1;
                        MMA16816(acc[i][jn], ar[i], brT[jj][pr * 2], brT[jj][pr * 2 + 1]);
                    }
            }
        };

        load_stage(0, sb0); CP_COMMIT();
        for (int j = 0; j < NCHUNK; j++) {
            asm volatile("cp.async.wait_group 0;" ::: "memory");
            __syncthreads();
            if (j + 1 < NCHUNK)
                load_stage(j + 1, sb0 + ((j + 1) & 1) * BUFSZ);
            CP_COMMIT();
            uint32_t base = sb0 + (j & 1) * BUFSZ;
            mma_pass(base,           base + BHOFF);
            mma_pass(base,           base + BLOFF);
            mma_pass(base + AOFF_LO, base + BHOFF);
        }

#pragma unroll
        for (int i = 0; i < 4; i++) {
#pragma unroll
            for (int jn = 0; jn < 8; jn++) {
                int r = m0 + wm + i * 16 + (lane >> 2);
                int cc = n0 + wn + jn * 8 + 2 * (lane & 3);
                float2 v0 = make_float2(acc[i][jn][0], acc[i][jn][1]);
                float2 v1 = make_float2(acc[i][jn][2], acc[i][jn][3]);
                *(float2*)(Cb + (long)r * HW + cc)       = v0;
                *(float2*)(Cb + (long)(r + 8) * HW + cc) = v1;
            }
        }
    } else {
        const int wm = (wid >> 1) << 5;
        float acc[2][8][4];
#pragma unroll
        for (int i = 0; i < 2; i++)
#pragma unroll
            for (int j = 0; j < 8; j++)
#pragma unroll
                for (int v = 0; v < 4; v++) acc[i][j][v] = 0.f;

        auto load_stage = [&](int j, uint32_t db) {
#pragma unroll
            for (int it = 0; it < 2; it++) {
                int row = (tid >> 2) + it * 32, seg = tid & 3;
                const __nv_bfloat16* arow = Ab + (long)(m0 + row) * KPA + j * 32 + seg * 8;
                CP16(db + row * ASTR + seg * 16, arow);
                CP16(db + AOFF_LO + row * ASTR + seg * 16, arow + 192);
            }
            loadB(j, db);
        };

        auto mma_pass = [&](uint32_t ab, uint32_t bb) {
#pragma unroll
            for (int ks = 0; ks < 2; ks++) {
                uint32_t ar[2][4], brT[4][4];
#pragma unroll
                for (int i = 0; i < 2; i++)
                    LDSM4(ar[i][0], ar[i][1], ar[i][2], ar[i][3],
                          ab + (wm + i * 16 + a_r) * ASTR + ks * 32 + a_ko);
#pragma unroll
                for (int j = 0; j < 4; j++)
                    LDSM4T(brT[j][0], brT[j][1], brT[j][2], brT[j][3],
                           bb + (ks * 16 + bt_k) * BSTR + wn * 2 + j * 32 + bt_n);
#pragma unroll
                for (int i = 0; i < 2; i++)
#pragma unroll
                    for (int jn = 0; jn < 8; jn++) {
                        int jj = jn >> 1, pr = jn & 1;
                        MMA16816(acc[i][jn], ar[i], brT[jj][pr * 2], brT[jj][pr * 2 + 1]);
                    }
            }
        };

        load_stage(0, sb0); CP_COMMIT();
        for (int j = 0; j < NCHUNK; j++) {
            asm volatile("cp.async.wait_group 0;" ::: "memory");
            __syncthreads();
            if (j + 1 < NCHUNK)
                load_stage(j + 1, sb0 + ((j + 1) & 1) * BUFSZ);
            CP_COMMIT();
            uint32_t base = sb0 + (j & 1) * BUFSZ;
            mma_pass(base,           base + BHOFF);
            mma_pass(base,           base + BLOFF);
            mma_pass(base + AOFF_LO, base + BHOFF);
        }

#pragma unroll
        for (int i = 0; i < 2; i++) {
#pragma unroll
            for (int jn = 0; jn < 8; jn++) {
                int r = m0 + wm + i * 16 + (lane >> 2);
                int cc = n0 + wn + jn * 8 + 2 * (lane & 3);
                float2 v0 = make_float2(acc[i][jn][0], acc[i][jn][1]);
                float2 v1 = make_float2(acc[i][jn][2], acc[i][jn][3]);
                *(float2*)(Cb + (long)r * HW + cc)       = v0;
                *(float2*)(Cb + (long)(r + 8) * HW + cc) = v1;
            }
        }
    }
}

// ---------------- split X into bf16 hi/lo planes ----------------
__global__ __launch_bounds__(256) void splitX_k(const float* __restrict__ src,
                                                __nv_bfloat16* __restrict__ dhi,
                                                __nv_bfloat16* __restrict__ dlo)
{
    long i4 = ((long)blockIdx.x * 256 + threadIdx.x) << 2;
    float4 v = *(const float4*)(src + i4);
    float hx = __bfloat162float(__float2bfloat16(v.x));
    float hy = __bfloat162float(__float2bfloat16(v.y));
    float hz = __bfloat162float(__float2bfloat16(v.z));
    float hw_ = __bfloat162float(__float2bfloat16(v.w));
    uint2 ph = make_uint2(pkbf(v.x, v.y), pkbf(v.z, v.w));
    uint2 pl = make_uint2(pkbf(v.x - hx, v.y - hy), pkbf(v.z - hz, v.w - hw_));
    *(uint2*)(dhi + i4) = ph;
    *(uint2*)(dlo + i4) = pl;
}

// ---------------- split A-side: src fp32 [Msrc][192] -> dst bf16 [Msrc][hi|lo] ------
__global__ __launch_bounds__(256) void splitA_k(const float* __restrict__ src,
                                                __nv_bfloat16* __restrict__ dst,
                                                int Msrc)
{
    int idx = blockIdx.x * 256 + threadIdx.x;
    int m = idx / DIMC, cc = idx - m * DIMC;
    float v = src[idx];
    __nv_bfloat16 hi = __float2bfloat16(v);
    dst[(long)m * KPA + cc]       = hi;
    dst[(long)m * KPA + 192 + cc] = __float2bfloat16(v - __bfloat162float(hi));
}

// ---------------- depthwise 3x3 tiled, per-batch pointers --------------------
__global__ __launch_bounds__(256) void dwconv_k(const float* __restrict__ wdw,
                                                const float* __restrict__ inb,
                                                float* __restrict__ dwb,
                                                __nv_bfloat16* __restrict__ vhib,
                                                __nv_bfloat16* __restrict__ vlob)
{
    __shared__ float s[18][128];
    int blk   = blockIdx.x;
    int strip = blk & 7;
    int ch    = blk >> 3;                   // 0..575
    const float* in = inb + (long)ch * HW;
    const int tid = threadIdx.x;

    float w[9];
#pragma unroll
    for (int i = 0; i < 9; i++) w[i] = __ldg(wdw + ch * 9 + i);

    const int y0 = strip << 4;
    for (int i = tid; i < 576; i += 256) {
        int r = i >> 5, c4 = (i & 31) << 2;
        int gy = y0 - 1 + r;
        float4 v = (gy >= 0 && gy < IMH)
                     ? *(const float4*)(in + gy * IMW + c4)
                     : make_float4(0.f, 0.f, 0.f, 0.f);
        *(float4*)&s[r][c4] = v;
    }
    __syncthreads();

    const int ty = (tid >> 5) << 1;
    const int x0 = (tid & 31) << 2;
    float o0[4] = {0.f, 0.f, 0.f, 0.f};
    float o1[4] = {0.f, 0.f, 0.f, 0.f};
#pragma unroll
    for (int r = 0; r < 4; r++) {
        const float* sr = s[ty + r];
        float vm = (x0 > 0)   ? sr[x0 - 1] : 0.f;
        float v0 = sr[x0],     v1 = sr[x0 + 1];
        float v2 = sr[x0 + 2], v3 = sr[x0 + 3];
        float vp = (x0 < 124) ? sr[x0 + 4] : 0.f;
        if (r < 3) {
            float wa = w[r * 3], wb = w[r * 3 + 1], wc = w[r * 3 + 2];
            o0[0] = fmaf(wa, vm, fmaf(wb, v0, fmaf(wc, v1, o0[0])));
            o0[1] = fmaf(wa, v0, fmaf(wb, v1, fmaf(wc, v2, o0[1])));
            o0[2] = fmaf(wa, v1, fmaf(wb, v2, fmaf(wc, v3, o0[2])));
            o0[3] = fmaf(wa, v2, fmaf(wb, v3, fmaf(wc, vp, o0[3])));
        }
        if (r >= 1) {
            float wa = w[(r - 1) * 3], wb = w[(r - 1) * 3 + 1], wc = w[(r - 1) * 3 + 2];
            o1[0] = fmaf(wa, vm, fmaf(wb, v0, fmaf(wc, v1, o1[0])));
            o1[1] = fmaf(wa, v0, fmaf(wb, v1, fmaf(wc, v2, o1[1])));
            o1[2] = fmaf(wa, v1, fmaf(wb, v2, fmaf(wc, v3, o1[2])));
            o1[3] = fmaf(wa, v2, fmaf(wb, v3, fmaf(wc, vp, o1[3])));
        }
    }
    int sp0 = (y0 + ty) * IMW + x0;
    int sp1 = sp0 + IMW;
    if (ch < 2 * DIMC) {
        float* op = dwb + (long)ch * HW;
        *(float4*)(op + sp0) = make_float4(o0[0], o0[1], o0[2], o0[3]);
        *(float4*)(op + sp1) = make_float4(o1[0], o1[1], o1[2], o1[3]);
    } else {
        long voff = (long)(ch - 2 * DIMC) * HW;
        float h00 = __bfloat162float(__float2bfloat16(o0[0]));
        float h01 = __bfloat162float(__float2bfloat16(o0[1]));
        float h02 = __bfloat162float(__float2bfloat16(o0[2]));
        float h03 = __bfloat162float(__float2bfloat16(o0[3]));
        float h10 = __bfloat162float(__float2bfloat16(o1[0]));
        float h11 = __bfloat162float(__float2bfloat16(o1[1]));
        float h12 = __bfloat162float(__float2bfloat16(o1[2]));
        float h13 = __bfloat162float(__float2bfloat16(o1[3]));
        *(uint2*)(vhib + voff + sp0) = make_uint2(pkbf(o0[0], o0[1]), pkbf(o0[2], o0[3]));
        *(uint2*)(vhib + voff + sp1) = make_uint2(pkbf(o1[0], o1[1]), pkbf(o1[2], o1[3]));
        *(uint2*)(vlob + voff + sp0) = make_uint2(pkbf(o0[0] - h00, o0[1] - h01),
                                                  pkbf(o0[2] - h02, o0[3] - h03));
        *(uint2*)(vlob + voff + sp1) = make_uint2(pkbf(o1[0] - h10, o1[1] - h11),
                                                  pkbf(o1[2] - h12, o1[3] - h13));
    }
}

// ---------------- attn partials, per-batch, 2x3 register-blocked, 96 threads ---------
__global__ __launch_bounds__(96) void attnpart_k(int b)
{
    int h = blockIdx.x;
    int split = blockIdx.y;
    int bh = b * NH + h;
    const int tid = threadIdx.x;
    const int cb = tid >> 3, db = tid & 7;
    const int c0 = cb << 1, d0 = db * 3;
    __shared__ float qs[24 * 68];
    __shared__ float ks[24 * 68];
    const float* qbase = g_dw + ((long)b * C3 + h * HD) * HW;
    const float* kbase = qbase + (long)DIMC * HW;
    float4 a_[2][3];
#pragma unroll
    for (int i = 0; i < 2; i++)
#pragma unroll
        for (int j = 0; j < 3; j++) a_[i][j] = make_float4(0.f, 0.f, 0.f, 0.f);
    float4 qq[2] = {{0,0,0,0}, {0,0,0,0}};
    float4 kk[3] = {{0,0,0,0}, {0,0,0,0}, {0,0,0,0}};
    const bool doq = (db == 0), dok = (cb == 0);
    int n0 = split * (HW / NSPLIT);
    int n1 = n0 + (HW / NSPLIT);
    for (; n0 < n1; n0 += 64) {
        for (int i = tid; i < 768; i += 96) {
            int m = (i >= 384);
            int j = i - (m ? 384 : 0);
            int r = j >> 4, c4 = j & 15;
            const float* src = (m ? kbase : qbase) + (long)r * HW + n0 + (c4 << 2);
            float* dst = (m ? ks : qs) + r * 68 + (c4 << 2);
            *(float4*)dst = *(const float4*)src;
        }
        __syncthreads();
#pragma unroll
        for (int j = 0; j < 16; j++) {
            float4 q0 = *(const float4*)&qs[ c0      * 68 + (j << 2)];
            float4 q1 = *(const float4*)&qs[(c0 + 1) * 68 + (j << 2)];
            float4 k0 = *(const float4*)&ks[ d0      * 68 + (j << 2)];
            float4 k1 = *(const float4*)&ks[(d0 + 1) * 68 + (j << 2)];
            float4 k2 = *(const float4*)&ks[(d0 + 2) * 68 + (j << 2)];
            float4 qv[2] = {q0, q1};
            float4 kv[3] = {k0, k1, k2};
#pragma unroll
            for (int i = 0; i < 2; i++)
#pragma unroll
                for (int jj = 0; jj < 3; jj++) {
                    a_[i][jj].x = fmaf(qv[i].x, kv[jj].x, a_[i][jj].x);
                    a_[i][jj].y = fmaf(qv[i].y, kv[jj].y, a_[i][jj].y);
                    a_[i][jj].z = fmaf(qv[i].z, kv[jj].z, a_[i][jj].z);
                    a_[i][jj].w = fmaf(qv[i].w, kv[jj].w, a_[i][jj].w);
                }
            if (doq) {
#pragma unroll
                for (int i = 0; i < 2; i++) {
                    qq[i].x = fmaf(qv[i].x, qv[i].x, qq[i].x);
                    qq[i].y = fmaf(qv[i].y, qv[i].y, qq[i].y);
                    qq[i].z = fmaf(qv[i].z, qv[i].z, qq[i].z);
                    qq[i].w = fmaf(qv[i].w, qv[i].w, qq[i].w);
                }
            }
            if (dok) {
#pragma unroll
                for (int jj = 0; jj < 3; jj++) {
                    kk[jj].x = fmaf(kv[jj].x, kv[jj].x, kk[jj].x);
                    kk[jj].y = fmaf(kv[jj].y, kv[jj].y, kk[jj].y);
                    kk[jj].z = fmaf(kv[jj].z, kv[jj].z, kk[jj].z);
                    kk[jj].w = fmaf(kv[jj].w, kv[jj].w, kk[jj].w);
                }
            }
        }
        __syncthreads();
    }
    long pbase = ((long)split * 64 + bh);
    float* ap = g_attn_part + pbase * 576;
#pragma unroll
    for (int i = 0; i < 2; i++)
#pragma unroll
        for (int jj = 0; jj < 3; jj++)
            ap[(c0 + i) * 24 + d0 + jj] =
                (a_[i][jj].x + a_[i][jj].y) + (a_[i][jj].z + a_[i][jj].w);
    float* np = g_np + pbase * 48;
    if (doq) {
        np[c0]     = (qq[0].x + qq[0].y) + (qq[0].z + qq[0].w);
        np[c0 + 1] = (qq[1].x + qq[1].y) + (qq[1].z + qq[1].w);
    }
    if (dok) {
#pragma unroll
        for (int jj = 0; jj < 3; jj++)
            np[24 + d0 + jj] = (kk[jj].x + kk[jj].y) + (kk[jj].z + kk[jj].w);
    }
}

// ---------------- combine splits + norms, scale, softmax ----------------
__global__ __launch_bounds__(576) void softmax_k(const float* __restrict__ temp)
{
    int bh = blockIdx.x; int h = bh & 7;
    int tid = threadIdx.x;
    int c = tid / 24, d = tid - c * 24;
    float s = 0.f;
#pragma unroll
    for (int sp = 0; sp < NSPLIT; sp++)
        s += g_attn_part[((long)sp * 64 + bh) * 576 + tid];
    __shared__ float sinv[48];
    if (tid < 48) {
        float t = 0.f;
#pragma unroll
        for (int sp = 0; sp < NSPLIT; sp++)
            t += g_np[((long)sp * 64 + bh) * 48 + tid];
        sinv[tid] = 1.0f / fmaxf(sqrtf(t), 1e-12f);
    }
    __syncthreads();
    __shared__ float as_[24][25];
    as_[c][d] = s * sinv[c] * sinv[24 + d] * temp[h];
    __syncthreads();
    __shared__ float rowmax[24], rowsum[24];
    if (tid < 24) {
        float m = -1e30f;
#pragma unroll
        for (int j = 0; j < 24; j++) m = fmaxf(m, as_[tid][j]);
        float sum = 0.f;
#pragma unroll
        for (int j = 0; j < 24; j++) sum += expf(as_[tid][j] - m);
        rowmax[tid] = m; rowsum[tid] = sum;
    }
    __syncthreads();
    g_attn[(long)bh * 576 + tid] = expf(as_[c][d] - rowmax[c]) / rowsum[c];
}

// ---------------- M_b = W_out * blockdiag(attn_b) -> bf16 A [hi|lo] ----
__global__ __launch_bounds__(256) void buildM_k(const float* __restrict__ wout)
{
    int idx = blockIdx.x * 256 + threadIdx.x;
    int b = blockIdx.y;
    int o  = idx / DIMC, kk = idx - o * DIMC;
    int h  = kk / HD,    d  = kk - h * HD;
    const float* wrow = wout + o * DIMC + h * HD;
    const float* arow = g_attn + (long)(b * NH + h) * (HD * HD) + d;
    float s = 0.f;
#pragma unroll
    for (int cc = 0; cc < HD; cc++)
        s = fmaf(wrow[cc], arow[cc * HD], s);
    __nv_bfloat16 hi = __float2bfloat16(s);
    __nv_bfloat16* dst = g_m2 + (long)b * (DIMC * KPA) + (long)o * KPA + kk;
    dst[0]   = hi;
    dst[192] = __float2bfloat16(s - __bfloat162float(hi));
}

// ---------------- launch (multi-stream fork/join: dw+ap overlap next batch's gemm1) ----------
extern "C" void kernel_launch(void* const* d_in, const int* in_sizes, int n_in,
                              void* d_out, int out_size)
{
    const float* x      = (const float*)d_in[0];
    const float* w_qkv  = (const float*)d_in[1];
    const float* w_dw   = (const float*)d_in[2];
    const float* w_out  = (const float*)d_in[3];
    const float* temp   = (const float*)d_in[4];
    float* out = (float*)d_out;

    float *p_qkv, *p_dw;
    __nv_bfloat16 *p_w1, *p_m2, *p_xhi, *p_xlo, *p_vhi, *p_vlo;
    cudaGetSymbolAddress((void**)&p_qkv, g_qkv);
    cudaGetSymbolAddress((void**)&p_dw,  g_dw);
    cudaGetSymbolAddress((void**)&p_w1,  g_w1);
    cudaGetSymbolAddress((void**)&p_m2,  g_m2);
    cudaGetSymbolAddress((void**)&p_xhi, g_xhi);
    cudaGetSymbolAddress((void**)&p_xlo, g_xlo);
    cudaGetSymbolAddress((void**)&p_vhi, g_vhi);
    cudaGetSymbolAddress((void**)&p_vlo, g_vlo);

    // lazy one-time stream/event creation (first call is the uncaptured correctness run)
    static cudaStream_t s2 = nullptr;
    static cudaEvent_t ev1[BATCH], ev2;
    if (!s2) {
        cudaStreamCreateWithFlags(&s2, cudaStreamNonBlocking);
        for (int b = 0; b < BATCH; b++)
            cudaEventCreateWithFlags(&ev1[b], cudaEventDisableTiming);
        cudaEventCreateWithFlags(&ev2, cudaEventDisableTiming);
    }

    cudaFuncSetAttribute(hmma_gemm, cudaFuncAttributeMaxDynamicSharedMemorySize, SMEM_G);

    // 0) weight/X preprocessing on origin stream
    splitA_k<<<(C3 * DIMC) / 256, 256>>>(w_qkv, p_w1, C3);
    splitX_k<<<(BATCH * DIMC * HW) / 1024, 256>>>(x, p_xhi, p_xlo);

    // 1) per-batch gemm1 on origin; record completion events
    for (int b = 0; b < BATCH; b++) {
        hmma_gemm<<<dim3(HW / 128, 5, 1), 128, SMEM_G>>>(
            p_w1, p_xhi + (long)b * DIMC * HW, p_xlo + (long)b * DIMC * HW,
            p_qkv + (long)b * C3 * HW, C3, 0L, 0L, 0L);
        cudaEventRecord(ev1[b], 0);
    }

    // 2) dwconv + attnpart per batch on side stream (overlaps later gemm1 batches)
    for (int b = 0; b < BATCH; b++) {
        cudaStreamWaitEvent(s2, ev1[b], 0);
        dwconv_k<<<C3 * 8, 256, 0, s2>>>(
            w_dw, p_qkv + (long)b * C3 * HW, p_dw + (long)b * C3 * HW,
            p_vhi + (long)b * DIMC * HW, p_vlo + (long)b * DIMC * HW);
        attnpart_k<<<dim3(NH, NSPLIT), 96, 0, s2>>>(b);
    }
    cudaEventRecord(ev2, s2);
    cudaStreamWaitEvent(0, ev2, 0);

    // 3) combine + scale + softmax
    softmax_k<<<BATCH * NH, 576>>>(temp);

    // 4) M_b = W_out * blockdiag(attn_b) -> bf16 A [hi|lo]
    buildM_k<<<dim3((DIMC * DIMC) / 256, BATCH), 256>>>(w_out);

    // 5) out = M_b @ V
    hmma_gemm<<<dim3(HW / 128, 2, BATCH), 128, SMEM_G>>>(
        p_m2, p_vhi, p_vlo, out, DIMC, (long)DIMC * KPA, (long)DIMC * HW, (long)DIMC * HW);
}